// round 2
// baseline (speedup 1.0000x reference)
#include <cuda_runtime.h>
#include <stdint.h>

// ---------------------------------------------------------------------------
// LoraSubnet: exact top-10% mask of |scores| with stable-sort tie-break by
// flat index, two independent 16,777,216-element fp32 matrices.
//
// 3-kernel pipeline (graph-capturable, scratch in __device__ globals):
//   K1 hist1_select1 : 8192-bin histogram of absbits[30:18] (smem privatized);
//                      last block per matrix selects the prefix bin containing
//                      rank j and the remaining rank rem1. Resets cand count.
//   K2 hist2_select2 : 262144-bin histogram of absbits[17:0] for elements in
//                      the prefix; simultaneously appends (bits18, idx) of all
//                      prefix-matching elements to a candidate list
//                      (warp-aggregated). Last block per matrix selects the
//                      exact threshold bits T32 + tie rank r, and resolves the
//                      tie-break index threshold from the candidate list.
//   K3 mask          : out = (bits>T32) || (bits==T32 && idx>=idx_thresh);
//                      also zeroes the histograms for the next graph replay
//                      (module-load zero-init covers the first invocation).
//
// Assumes n (elements per matrix) is a multiple of 128 so every warp in the
// grid-stride loops executes full-warp iterations (true here: n = 2^24).
// ---------------------------------------------------------------------------

#define H1_BITS 13
#define H1_BINS (1 << H1_BITS)     // 8192
#define H2_BITS 18
#define H2_BINS (1 << H2_BITS)     // 262144
#define ABS_MASK 0x7fffffffu
#define CAND_CAP (1u << 24)        // == n: overflow impossible

#define G1X 296
#define G1T 512
#define G2X 1184
#define G2T 256
#define GMX 1184
#define GMT 256

struct SelState {
    unsigned prefix;      // selected 13-bit prefix of abs bits
    unsigned rem1;        // rank remaining within prefix group
    unsigned T32;         // exact abs-bits threshold (bits of rank-j element)
    unsigned idx_thresh;  // tied elems with idx >= idx_thresh get 1
};

__device__ unsigned g_hist1[2][H1_BINS];
__device__ unsigned g_hist2[2][H2_BINS];
__device__ unsigned long long g_cand[2][CAND_CAP];
__device__ unsigned g_cand_cnt[2];
__device__ unsigned g_done1[2];
__device__ unsigned g_done2[2];
__device__ SelState g_state[2];

// ---------------------------------------------------------------------------
// K1: 13-bit histogram + fused select1 (last block per matrix)
// ---------------------------------------------------------------------------
__global__ __launch_bounds__(G1T) void hist1_select1_kernel(
    const float4* __restrict__ A, const float4* __restrict__ B,
    int n4, unsigned j) {
    __shared__ unsigned sh[H1_BINS];
    const int m = blockIdx.y;
    const float4* src = m ? B : A;

    for (int i = threadIdx.x; i < H1_BINS; i += G1T) sh[i] = 0;
    __syncthreads();

    const int stride = G1T * gridDim.x;
    for (int i = blockIdx.x * G1T + threadIdx.x; i < n4; i += stride) {
        float4 v = __ldg(src + i);
        atomicAdd(&sh[(__float_as_uint(v.x) & ABS_MASK) >> H2_BITS], 1u);
        atomicAdd(&sh[(__float_as_uint(v.y) & ABS_MASK) >> H2_BITS], 1u);
        atomicAdd(&sh[(__float_as_uint(v.z) & ABS_MASK) >> H2_BITS], 1u);
        atomicAdd(&sh[(__float_as_uint(v.w) & ABS_MASK) >> H2_BITS], 1u);
    }
    __syncthreads();

    unsigned* gh = g_hist1[m];
    for (int i = threadIdx.x; i < H1_BINS; i += G1T) {
        unsigned c = sh[i];
        if (c) atomicAdd(&gh[i], c);
    }

    // ---- last-block-done handshake ----
    __threadfence();
    __syncthreads();
    __shared__ unsigned s_isLast;
    if (threadIdx.x == 0)
        s_isLast = (atomicAdd(&g_done1[m], 1u) == gridDim.x - 1u) ? 1u : 0u;
    __syncthreads();
    if (!s_isLast) return;
    __threadfence();

    // ---- select1: find prefix bin containing rank j ----
    constexpr int PER = H1_BINS / G1T;  // 16
    unsigned bins[PER];
    unsigned local = 0;
    const int base = threadIdx.x * PER;
#pragma unroll
    for (int i = 0; i < PER; i++) {
        bins[i] = gh[base + i];
        local += bins[i];
    }
    __shared__ unsigned s_scan[G1T];
    s_scan[threadIdx.x] = local;
    __syncthreads();
    for (int off = 1; off < G1T; off <<= 1) {
        unsigned t = (threadIdx.x >= off) ? s_scan[threadIdx.x - off] : 0u;
        __syncthreads();
        s_scan[threadIdx.x] += t;
        __syncthreads();
    }
    const unsigned incl = s_scan[threadIdx.x];
    const unsigned excl = incl - local;
    if (j >= excl && j < incl) {
        unsigned acc = excl;
#pragma unroll
        for (int i = 0; i < PER; i++) {
            if (j < acc + bins[i]) {
                g_state[m].prefix = (unsigned)(base + i);
                g_state[m].rem1 = j - acc;
                break;
            }
            acc += bins[i];
        }
    }
    if (threadIdx.x == 0) {
        g_cand_cnt[m] = 0;   // reset for K2
        g_done1[m] = 0;      // reset for next replay
    }
}

// ---------------------------------------------------------------------------
// K2: 18-bit histogram within prefix + candidate gather + fused select2/ties
// ---------------------------------------------------------------------------
__global__ __launch_bounds__(G2T) void hist2_select2_kernel(
    const float4* __restrict__ A, const float4* __restrict__ B, int n4) {
    const int m = blockIdx.y;
    const float4* src = m ? B : A;
    const unsigned pfx = g_state[m].prefix;
    unsigned* gh = g_hist2[m];
    unsigned long long* cand = g_cand[m];
    const unsigned lane = threadIdx.x & 31u;
    const unsigned lowmask = (lane == 0) ? 0u : (0xffffffffu >> (32 - lane));

    const int stride = G2T * gridDim.x;
    for (int i = blockIdx.x * G2T + threadIdx.x; i < n4; i += stride) {
        float4 v = __ldg(src + i);
        unsigned bx = __float_as_uint(v.x) & ABS_MASK;
        unsigned by = __float_as_uint(v.y) & ABS_MASK;
        unsigned bz = __float_as_uint(v.z) & ABS_MASK;
        unsigned bw = __float_as_uint(v.w) & ABS_MASK;
        bool px = (bx >> H2_BITS) == pfx;
        bool py = (by >> H2_BITS) == pfx;
        bool pz = (bz >> H2_BITS) == pfx;
        bool pw = (bw >> H2_BITS) == pfx;
        // warp-aggregated candidate append (full warps guaranteed)
        unsigned mx = __ballot_sync(0xffffffffu, px);
        unsigned my = __ballot_sync(0xffffffffu, py);
        unsigned mz = __ballot_sync(0xffffffffu, pz);
        unsigned mw = __ballot_sync(0xffffffffu, pw);
        unsigned tot = __popc(mx) + __popc(my) + __popc(mz) + __popc(mw);
        if (tot == 0) continue;
        unsigned basec = 0;
        if (lane == 0) basec = atomicAdd(&g_cand_cnt[m], tot);
        basec = __shfl_sync(0xffffffffu, basec, 0);
        const unsigned idx = 4u * (unsigned)i;
        if (px) {
            atomicAdd(&gh[bx & (H2_BINS - 1)], 1u);
            unsigned p = basec + __popc(mx & lowmask);
            cand[p] = ((unsigned long long)(bx & (H2_BINS - 1)) << 32) | idx;
        }
        if (py) {
            atomicAdd(&gh[by & (H2_BINS - 1)], 1u);
            unsigned p = basec + __popc(mx) + __popc(my & lowmask);
            cand[p] = ((unsigned long long)(by & (H2_BINS - 1)) << 32) | (idx + 1u);
        }
        if (pz) {
            atomicAdd(&gh[bz & (H2_BINS - 1)], 1u);
            unsigned p = basec + __popc(mx) + __popc(my) + __popc(mz & lowmask);
            cand[p] = ((unsigned long long)(bz & (H2_BINS - 1)) << 32) | (idx + 2u);
        }
        if (pw) {
            atomicAdd(&gh[bw & (H2_BINS - 1)], 1u);
            unsigned p = basec + __popc(mx) + __popc(my) + __popc(mz) + __popc(mw & lowmask);
            cand[p] = ((unsigned long long)(bw & (H2_BINS - 1)) << 32) | (idx + 3u);
        }
    }

    // ---- last-block-done handshake ----
    __threadfence();
    __syncthreads();
    __shared__ unsigned s_isLast;
    if (threadIdx.x == 0)
        s_isLast = (atomicAdd(&g_done2[m], 1u) == gridDim.x - 1u) ? 1u : 0u;
    __syncthreads();
    if (!s_isLast) return;
    __threadfence();

    // ---- select2: hierarchical rank-select over 262144 bins ----
    // per thread: 1024 bins as 256 uint4 loads, 16 register sub-sums of 64
    const uint4* h4 = (const uint4*)gh;
    unsigned sub[16];
    unsigned total = 0;
    const int b4 = threadIdx.x * 256;
    for (int s = 0; s < 16; s++) {
        unsigned acc = 0;
#pragma unroll
        for (int q = 0; q < 16; q++) {
            uint4 v = h4[b4 + s * 16 + q];
            acc += v.x + v.y + v.z + v.w;
        }
        sub[s] = acc;
        total += acc;
    }
    __shared__ unsigned s_scan2[G2T];
    s_scan2[threadIdx.x] = total;
    __syncthreads();
    for (int off = 1; off < G2T; off <<= 1) {
        unsigned t = (threadIdx.x >= off) ? s_scan2[threadIdx.x - off] : 0u;
        __syncthreads();
        s_scan2[threadIdx.x] += t;
        __syncthreads();
    }
    const unsigned incl = s_scan2[threadIdx.x];
    const unsigned excl = incl - total;
    const unsigned rank = g_state[m].rem1;

    __shared__ unsigned s_bin, s_rem;
    if (rank >= excl && rank < incl) {
        unsigned acc = excl;
        int s = 0;
        for (; s < 16; s++) {
            if (rank < acc + sub[s]) break;
            acc += sub[s];
        }
        const int binbase = threadIdx.x * 1024 + s * 64;
        for (int q = 0; q < 64; q++) {
            unsigned cbin = gh[binbase + q];
            if (rank < acc + cbin) {
                s_bin = (unsigned)(binbase + q);
                s_rem = rank - acc;
                break;
            }
            acc += cbin;
        }
    }
    __syncthreads();
    const unsigned bin = s_bin;
    const unsigned r = s_rem;
    const unsigned T32 = (pfx << H2_BITS) | bin;

    // ---- tie resolution from candidate list ----
    unsigned idx_thresh = 0;
    if (r > 0) {
        const unsigned cnt = g_cand_cnt[m];  // <= CAND_CAP by construction
        __shared__ unsigned s_tcnt;
        __shared__ unsigned s_ans;
        __shared__ unsigned s_tie[4096];
        if (threadIdx.x == 0) s_tcnt = 0;
        __syncthreads();
        for (unsigned e = threadIdx.x; e < cnt; e += G2T) {
            unsigned long long ce = cand[e];
            if ((unsigned)(ce >> 32) == bin) {
                unsigned p = atomicAdd(&s_tcnt, 1u);
                if (p < 4096u) s_tie[p] = (unsigned)ce;
            }
        }
        __syncthreads();
        const unsigned tc = s_tcnt;
        if (tc <= 4096u) {
            // O(c^2) rank: find tied idx with exactly r smaller tied indices
            for (unsigned e = threadIdx.x; e < tc; e += G2T) {
                unsigned myi = s_tie[e];
                unsigned rk = 0;
                for (unsigned k = 0; k < tc; k++) rk += (s_tie[k] < myi) ? 1u : 0u;
                if (rk == r) s_ans = myi;
            }
        } else {
            // pathological fallback: binary search smallest X with
            // count(tied idx <= X) >= r+1
            __shared__ unsigned s_cnt;
            unsigned lo = 0, hi = 0xffffffffu;
            while (lo < hi) {
                unsigned mid = lo + ((hi - lo) >> 1);
                if (threadIdx.x == 0) s_cnt = 0;
                __syncthreads();
                unsigned loc = 0;
                for (unsigned e = threadIdx.x; e < cnt; e += G2T) {
                    unsigned long long ce = cand[e];
                    if ((unsigned)(ce >> 32) == bin && (unsigned)ce <= mid) loc++;
                }
                atomicAdd(&s_cnt, loc);
                __syncthreads();
                unsigned c = s_cnt;
                __syncthreads();
                if (c >= r + 1u) hi = mid; else lo = mid + 1u;
            }
            if (threadIdx.x == 0) s_ans = lo;
        }
        __syncthreads();
        idx_thresh = s_ans;
    }

    if (threadIdx.x == 0) {
        g_state[m].T32 = T32;
        g_state[m].idx_thresh = idx_thresh;
        g_done2[m] = 0;  // reset for next replay
    }
}

// ---------------------------------------------------------------------------
// K3: write mask + zero histograms for the next replay
// ---------------------------------------------------------------------------
__device__ __forceinline__ float keep(unsigned b, unsigned idx, unsigned T,
                                      unsigned it) {
    return (b > T || (b == T && idx >= it)) ? 1.0f : 0.0f;
}

__global__ __launch_bounds__(GMT) void mask_kernel(
    const float4* __restrict__ A, const float4* __restrict__ B,
    float4* __restrict__ out, int n4) {
    const int m = blockIdx.y;
    const float4* src = m ? B : A;
    float4* dst = out + (size_t)m * (size_t)n4;
    const unsigned T = g_state[m].T32;
    const unsigned it = g_state[m].idx_thresh;

    const int stride = GMT * gridDim.x;
    for (int i = blockIdx.x * GMT + threadIdx.x; i < n4; i += stride) {
        float4 v = __ldg(src + i);
        const unsigned idx = 4u * (unsigned)i;
        float4 o;
        o.x = keep(__float_as_uint(v.x) & ABS_MASK, idx + 0u, T, it);
        o.y = keep(__float_as_uint(v.y) & ABS_MASK, idx + 1u, T, it);
        o.z = keep(__float_as_uint(v.z) & ABS_MASK, idx + 2u, T, it);
        o.w = keep(__float_as_uint(v.w) & ABS_MASK, idx + 3u, T, it);
        dst[i] = o;
    }

    // zero histograms for the next graph replay (not read again this replay)
    const int tid = ((int)blockIdx.y * (int)gridDim.x + (int)blockIdx.x) * GMT
                    + (int)threadIdx.x;
    const int tot = (int)gridDim.x * 2 * GMT;
    unsigned* h2 = &g_hist2[0][0];
    for (int i = tid; i < 2 * H2_BINS; i += tot) h2[i] = 0;
    unsigned* h1 = &g_hist1[0][0];
    for (int i = tid; i < 2 * H1_BINS; i += tot) h1[i] = 0;
}

// ---------------------------------------------------------------------------
extern "C" void kernel_launch(void* const* d_in, const int* in_sizes, int n_in,
                              void* d_out, int out_size) {
    const float4* A = (const float4*)d_in[0];
    const float4* B = (const float4*)d_in[1];
    float4* out = (float4*)d_out;

    const unsigned n = (unsigned)in_sizes[0];  // 16,777,216 per matrix
    const int n4 = (int)(n / 4u);
    // Mirror Python int((1.0 - 0.1) * n) exactly (double arithmetic, truncate)
    const unsigned j = (unsigned)((1.0 - 0.1) * (double)n);

    dim3 g1(G1X, 2);
    hist1_select1_kernel<<<g1, G1T>>>(A, B, n4, j);

    dim3 g2(G2X, 2);
    hist2_select2_kernel<<<g2, G2T>>>(A, B, n4);

    dim3 gm(GMX, 2);
    mask_kernel<<<gm, GMT>>>(A, B, out, n4);
}

// round 5
// speedup vs baseline: 2.7710x; 2.7710x over previous
#include <cuda_runtime.h>
#include <stdint.h>

// ---------------------------------------------------------------------------
// LoraSubnet: exact top-10% mask of |scores| with stable-sort tie-break by
// flat index, two independent 16,777,216-element fp32 matrices.
//
// 4-kernel pipeline (graph-capturable, scratch in __device__ globals):
//   K1 hist1 : 8192-bin histogram of absbits[30:18] (smem privatized);
//              last block per matrix -> prefix bin containing rank j, rem1.
//   K2 hist2 : 262144-bin histogram of absbits[17:0] within prefix (global
//              atomics, ~1 hit/bin); last block -> exact T32 + tie-rank r.
//   K3 mask  : out = (bits > T32); appends indices with bits == T32 to a tiny
//              tie list (expected ~1-12 entries total); zeroes histograms
//              for the next graph replay.
//   K4 ties  : out[idx] = 1 for tied indices with index-rank >= r.
// ---------------------------------------------------------------------------

#define H1_BITS 13
#define H1_BINS (1 << H1_BITS)     // 8192
#define H2_BITS 18
#define H2_BINS (1 << H2_BITS)     // 262144
#define ABS_MASK 0x7fffffffu
#define TIE_CAP 16384

#define G1X 296
#define G1T 512
#define G2X 1184
#define G2T 256
#define GMX 1184
#define GMT 256

struct SelState {
    unsigned prefix;  // selected 13-bit prefix of abs bits
    unsigned rem1;    // rank remaining within prefix group
    unsigned T32;     // exact abs-bits threshold (bits of rank-j element)
    unsigned r;       // tie rank: r smallest-index ties are zeroed
};

__device__ unsigned g_hist1[2][H1_BINS];
__device__ unsigned g_hist2[2][H2_BINS];
__device__ unsigned g_tie_idx[2][TIE_CAP];
__device__ unsigned g_tie_cnt[2];
__device__ unsigned g_done1[2];
__device__ unsigned g_done2[2];
__device__ SelState g_state[2];

// ---------------------------------------------------------------------------
// K1: 13-bit histogram + fused select1 (last block per matrix)
// ---------------------------------------------------------------------------
__global__ __launch_bounds__(G1T) void hist1_kernel(
    const float4* __restrict__ A, const float4* __restrict__ B,
    int n4, unsigned j) {
    __shared__ unsigned sh[H1_BINS];
    const int m = blockIdx.y;
    const float4* src = m ? B : A;

    for (int i = threadIdx.x; i < H1_BINS; i += G1T) sh[i] = 0;
    __syncthreads();

    const int stride = G1T * gridDim.x;
    int i = blockIdx.x * G1T + threadIdx.x;
    // unrolled x2 for MLP: two independent loads in flight
    for (; i + stride < n4; i += 2 * stride) {
        float4 v0 = __ldg(src + i);
        float4 v1 = __ldg(src + i + stride);
        atomicAdd(&sh[(__float_as_uint(v0.x) & ABS_MASK) >> H2_BITS], 1u);
        atomicAdd(&sh[(__float_as_uint(v0.y) & ABS_MASK) >> H2_BITS], 1u);
        atomicAdd(&sh[(__float_as_uint(v0.z) & ABS_MASK) >> H2_BITS], 1u);
        atomicAdd(&sh[(__float_as_uint(v0.w) & ABS_MASK) >> H2_BITS], 1u);
        atomicAdd(&sh[(__float_as_uint(v1.x) & ABS_MASK) >> H2_BITS], 1u);
        atomicAdd(&sh[(__float_as_uint(v1.y) & ABS_MASK) >> H2_BITS], 1u);
        atomicAdd(&sh[(__float_as_uint(v1.z) & ABS_MASK) >> H2_BITS], 1u);
        atomicAdd(&sh[(__float_as_uint(v1.w) & ABS_MASK) >> H2_BITS], 1u);
    }
    if (i < n4) {
        float4 v = __ldg(src + i);
        atomicAdd(&sh[(__float_as_uint(v.x) & ABS_MASK) >> H2_BITS], 1u);
        atomicAdd(&sh[(__float_as_uint(v.y) & ABS_MASK) >> H2_BITS], 1u);
        atomicAdd(&sh[(__float_as_uint(v.z) & ABS_MASK) >> H2_BITS], 1u);
        atomicAdd(&sh[(__float_as_uint(v.w) & ABS_MASK) >> H2_BITS], 1u);
    }
    __syncthreads();

    unsigned* gh = g_hist1[m];
    for (int k = threadIdx.x; k < H1_BINS; k += G1T) {
        unsigned c = sh[k];
        if (c) atomicAdd(&gh[k], c);
    }

    // ---- last-block-done handshake ----
    __threadfence();
    __syncthreads();
    __shared__ unsigned s_isLast;
    if (threadIdx.x == 0)
        s_isLast = (atomicAdd(&g_done1[m], 1u) == gridDim.x - 1u) ? 1u : 0u;
    __syncthreads();
    if (!s_isLast) return;
    __threadfence();

    // ---- select1: find prefix bin containing rank j ----
    constexpr int PER = H1_BINS / G1T;  // 16
    unsigned bins[PER];
    unsigned local = 0;
    const int base = threadIdx.x * PER;
#pragma unroll
    for (int q = 0; q < PER; q++) {
        bins[q] = gh[base + q];
        local += bins[q];
    }
    __shared__ unsigned s_scan[G1T];
    s_scan[threadIdx.x] = local;
    __syncthreads();
    for (int off = 1; off < G1T; off <<= 1) {
        unsigned t = (threadIdx.x >= off) ? s_scan[threadIdx.x - off] : 0u;
        __syncthreads();
        s_scan[threadIdx.x] += t;
        __syncthreads();
    }
    const unsigned incl = s_scan[threadIdx.x];
    const unsigned excl = incl - local;
    if (j >= excl && j < incl) {
        unsigned acc = excl;
#pragma unroll
        for (int q = 0; q < PER; q++) {
            if (j < acc + bins[q]) {
                g_state[m].prefix = (unsigned)(base + q);
                g_state[m].rem1 = j - acc;
                break;
            }
            acc += bins[q];
        }
    }
    if (threadIdx.x == 0) g_done1[m] = 0;  // reset for next replay
}

// ---------------------------------------------------------------------------
// K2: 18-bit histogram within prefix + fused select2 (last block per matrix)
// ---------------------------------------------------------------------------
__global__ __launch_bounds__(G2T) void hist2_kernel(
    const float4* __restrict__ A, const float4* __restrict__ B, int n4) {
    const int m = blockIdx.y;
    const float4* src = m ? B : A;
    const unsigned pfx = g_state[m].prefix;
    unsigned* gh = g_hist2[m];

    const int stride = G2T * gridDim.x;
    for (int i = blockIdx.x * G2T + threadIdx.x; i < n4; i += stride) {
        float4 v = __ldg(src + i);
        unsigned b;
        b = __float_as_uint(v.x) & ABS_MASK;
        if ((b >> H2_BITS) == pfx) atomicAdd(&gh[b & (H2_BINS - 1)], 1u);
        b = __float_as_uint(v.y) & ABS_MASK;
        if ((b >> H2_BITS) == pfx) atomicAdd(&gh[b & (H2_BINS - 1)], 1u);
        b = __float_as_uint(v.z) & ABS_MASK;
        if ((b >> H2_BITS) == pfx) atomicAdd(&gh[b & (H2_BINS - 1)], 1u);
        b = __float_as_uint(v.w) & ABS_MASK;
        if ((b >> H2_BITS) == pfx) atomicAdd(&gh[b & (H2_BINS - 1)], 1u);
    }

    // ---- last-block-done handshake ----
    __threadfence();
    __syncthreads();
    __shared__ unsigned s_isLast;
    if (threadIdx.x == 0)
        s_isLast = (atomicAdd(&g_done2[m], 1u) == gridDim.x - 1u) ? 1u : 0u;
    __syncthreads();
    if (!s_isLast) return;
    __threadfence();

    // ---- select2: hierarchical rank-select over 262144 bins ----
    // per thread: 1024 bins as 256 uint4 loads, 16 register sub-sums of 64
    const uint4* h4 = (const uint4*)gh;
    unsigned sub[16];
    unsigned total = 0;
    const int b4 = threadIdx.x * 256;
    for (int s = 0; s < 16; s++) {
        unsigned acc = 0;
#pragma unroll
        for (int q = 0; q < 16; q++) {
            uint4 v = h4[b4 + s * 16 + q];
            acc += v.x + v.y + v.z + v.w;
        }
        sub[s] = acc;
        total += acc;
    }
    __shared__ unsigned s_scan2[G2T];
    s_scan2[threadIdx.x] = total;
    __syncthreads();
    for (int off = 1; off < G2T; off <<= 1) {
        unsigned t = (threadIdx.x >= off) ? s_scan2[threadIdx.x - off] : 0u;
        __syncthreads();
        s_scan2[threadIdx.x] += t;
        __syncthreads();
    }
    const unsigned incl = s_scan2[threadIdx.x];
    const unsigned excl = incl - total;
    const unsigned rank = g_state[m].rem1;

    if (rank >= excl && rank < incl) {
        unsigned acc = excl;
        int s = 0;
        for (; s < 16; s++) {
            if (rank < acc + sub[s]) break;
            acc += sub[s];
        }
        const int binbase = threadIdx.x * 1024 + s * 64;
        for (int q = 0; q < 64; q++) {
            unsigned cbin = gh[binbase + q];
            if (rank < acc + cbin) {
                g_state[m].T32 = (pfx << H2_BITS) | (unsigned)(binbase + q);
                g_state[m].r = rank - acc;
                break;
            }
            acc += cbin;
        }
    }
    if (threadIdx.x == 0) g_done2[m] = 0;  // reset for next replay
}

// ---------------------------------------------------------------------------
// K3: mask write (strict >) + tiny tie-index collection + hist zeroing
// ---------------------------------------------------------------------------
__global__ __launch_bounds__(GMT) void mask_kernel(
    const float4* __restrict__ A, const float4* __restrict__ B,
    float4* __restrict__ out, int n4) {
    const int m = blockIdx.y;
    const float4* src = m ? B : A;
    float4* dst = out + (size_t)m * (size_t)n4;
    const unsigned T = g_state[m].T32;

    const int stride = GMT * gridDim.x;
    for (int i = blockIdx.x * GMT + threadIdx.x; i < n4; i += stride) {
        float4 v = __ldg(src + i);
        unsigned bx = __float_as_uint(v.x) & ABS_MASK;
        unsigned by = __float_as_uint(v.y) & ABS_MASK;
        unsigned bz = __float_as_uint(v.z) & ABS_MASK;
        unsigned bw = __float_as_uint(v.w) & ABS_MASK;
        float4 o;
        o.x = (bx > T) ? 1.0f : 0.0f;
        o.y = (by > T) ? 1.0f : 0.0f;
        o.z = (bz > T) ? 1.0f : 0.0f;
        o.w = (bw > T) ? 1.0f : 0.0f;
        dst[i] = o;
        // exact-equality ties are astronomically sparse (~1-12 per matrix)
        if (bx == T || by == T || bz == T || bw == T) {
            const unsigned idx = 4u * (unsigned)i;
            if (bx == T) {
                unsigned p = atomicAdd(&g_tie_cnt[m], 1u);
                if (p < TIE_CAP) g_tie_idx[m][p] = idx + 0u;
            }
            if (by == T) {
                unsigned p = atomicAdd(&g_tie_cnt[m], 1u);
                if (p < TIE_CAP) g_tie_idx[m][p] = idx + 1u;
            }
            if (bz == T) {
                unsigned p = atomicAdd(&g_tie_cnt[m], 1u);
                if (p < TIE_CAP) g_tie_idx[m][p] = idx + 2u;
            }
            if (bw == T) {
                unsigned p = atomicAdd(&g_tie_cnt[m], 1u);
                if (p < TIE_CAP) g_tie_idx[m][p] = idx + 3u;
            }
        }
    }

    // zero histograms for the next graph replay (not read again this replay)
    const int tid = ((int)blockIdx.y * (int)gridDim.x + (int)blockIdx.x) * GMT
                    + (int)threadIdx.x;
    const int tot = (int)gridDim.x * 2 * GMT;
    unsigned* h2 = &g_hist2[0][0];
    for (int k = tid; k < 2 * H2_BINS; k += tot) h2[k] = 0;
    unsigned* h1 = &g_hist1[0][0];
    for (int k = tid; k < 2 * H1_BINS; k += tot) h1[k] = 0;
}

// ---------------------------------------------------------------------------
// K4: resolve ties — kept iff index-rank among ties >= r
// ---------------------------------------------------------------------------
__global__ void tie_fix_kernel(float* __restrict__ out, unsigned n) {
    const int m = blockIdx.x;
    float* dst = out + (size_t)m * (size_t)n;
    unsigned tc = g_tie_cnt[m];
    if (tc > TIE_CAP) tc = TIE_CAP;
    const unsigned r = g_state[m].r;
    for (unsigned e = threadIdx.x; e < tc; e += blockDim.x) {
        const unsigned my = g_tie_idx[m][e];
        unsigned rk = 0;
        for (unsigned k = 0; k < tc; k++)
            rk += (g_tie_idx[m][k] < my) ? 1u : 0u;
        if (rk >= r) dst[my] = 1.0f;
    }
    __syncthreads();
    if (threadIdx.x == 0) g_tie_cnt[m] = 0;  // reset for next replay
}

// ---------------------------------------------------------------------------
extern "C" void kernel_launch(void* const* d_in, const int* in_sizes, int n_in,
                              void* d_out, int out_size) {
    const float4* A = (const float4*)d_in[0];
    const float4* B = (const float4*)d_in[1];
    float4* out = (float4*)d_out;

    const unsigned n = (unsigned)in_sizes[0];  // 16,777,216 per matrix
    const int n4 = (int)(n / 4u);
    // Mirror Python int((1.0 - 0.1) * n) exactly (double arithmetic, truncate)
    const unsigned j = (unsigned)((1.0 - 0.1) * (double)n);

    dim3 g1(G1X, 2);
    hist1_kernel<<<g1, G1T>>>(A, B, n4, j);

    dim3 g2(G2X, 2);
    hist2_kernel<<<g2, G2T>>>(A, B, n4);

    dim3 gm(GMX, 2);
    mask_kernel<<<gm, GMT>>>(A, B, out, n4);

    tie_fix_kernel<<<2, 256>>>((float*)d_out, n);
}

// round 7
// speedup vs baseline: 3.0229x; 1.0909x over previous
#include <cuda_runtime.h>
#include <stdint.h>

// ---------------------------------------------------------------------------
// LoraSubnet: exact top-10% mask of |scores| with stable-sort tie-break by
// flat index, two independent 16,777,216-element fp32 matrices.
//
// 3-kernel pipeline (graph-capturable, scratch in __device__ globals):
//   K1 hist1 : 8192-bin histogram of absbits[30:18] (smem privatized);
//              last block per matrix -> prefix bin containing rank j, rem1.
//   K2 hist2 : 262144 fine + 1024 coarse histogram of absbits[17:0] within
//              prefix (spread global atomics); last block does a 2-level
//              block-parallel rank-select (4KB coarse + 1KB fine) -> T32, r.
//   K3 mask  : out = (bits > T32); appends indices with bits == T32 to a tiny
//              tie list; zeroes histograms for the next replay; last block
//              per matrix resolves ties in-place (out[idx]=1 for rank >= r).
// ---------------------------------------------------------------------------

#define H1_BITS 13
#define H1_BINS (1 << H1_BITS)     // 8192
#define H2_BITS 18
#define H2_BINS (1 << H2_BITS)     // 262144
#define H2C_BINS 1024              // coarse: fine >> 8
#define ABS_MASK 0x7fffffffu
#define TIE_CAP 16384

#define G1X 296
#define G1T 512
#define G2X 1184
#define G2T 256
#define GMX 1184
#define GMT 256

struct SelState {
    unsigned prefix;  // selected 13-bit prefix of abs bits
    unsigned rem1;    // rank remaining within prefix group
    unsigned T32;     // exact abs-bits threshold (bits of rank-j element)
    unsigned r;       // tie rank: r smallest-index ties are zeroed
};

__device__ unsigned g_hist1[2][H1_BINS];
__device__ unsigned g_hist2[2][H2_BINS];
__device__ unsigned g_hist2c[2][H2C_BINS];
__device__ unsigned g_tie_idx[2][TIE_CAP];
__device__ unsigned g_tie_cnt[2];
__device__ unsigned g_done1[2];
__device__ unsigned g_done2[2];
__device__ unsigned g_done3[2];
__device__ SelState g_state[2];

// ---------------------------------------------------------------------------
// K1: 13-bit histogram + fused select1 (last block per matrix)
// ---------------------------------------------------------------------------
__global__ __launch_bounds__(G1T) void hist1_kernel(
    const float4* __restrict__ A, const float4* __restrict__ B,
    int n4, unsigned j) {
    __shared__ unsigned sh[H1_BINS];
    const int m = blockIdx.y;
    const float4* src = m ? B : A;

    for (int i = threadIdx.x; i < H1_BINS; i += G1T) sh[i] = 0;
    __syncthreads();

    const int stride = G1T * gridDim.x;
    int i = blockIdx.x * G1T + threadIdx.x;
    for (; i + stride < n4; i += 2 * stride) {
        float4 v0 = __ldg(src + i);
        float4 v1 = __ldg(src + i + stride);
        atomicAdd(&sh[(__float_as_uint(v0.x) & ABS_MASK) >> H2_BITS], 1u);
        atomicAdd(&sh[(__float_as_uint(v0.y) & ABS_MASK) >> H2_BITS], 1u);
        atomicAdd(&sh[(__float_as_uint(v0.z) & ABS_MASK) >> H2_BITS], 1u);
        atomicAdd(&sh[(__float_as_uint(v0.w) & ABS_MASK) >> H2_BITS], 1u);
        atomicAdd(&sh[(__float_as_uint(v1.x) & ABS_MASK) >> H2_BITS], 1u);
        atomicAdd(&sh[(__float_as_uint(v1.y) & ABS_MASK) >> H2_BITS], 1u);
        atomicAdd(&sh[(__float_as_uint(v1.z) & ABS_MASK) >> H2_BITS], 1u);
        atomicAdd(&sh[(__float_as_uint(v1.w) & ABS_MASK) >> H2_BITS], 1u);
    }
    if (i < n4) {
        float4 v = __ldg(src + i);
        atomicAdd(&sh[(__float_as_uint(v.x) & ABS_MASK) >> H2_BITS], 1u);
        atomicAdd(&sh[(__float_as_uint(v.y) & ABS_MASK) >> H2_BITS], 1u);
        atomicAdd(&sh[(__float_as_uint(v.z) & ABS_MASK) >> H2_BITS], 1u);
        atomicAdd(&sh[(__float_as_uint(v.w) & ABS_MASK) >> H2_BITS], 1u);
    }
    __syncthreads();

    unsigned* gh = g_hist1[m];
    for (int k = threadIdx.x; k < H1_BINS; k += G1T) {
        unsigned c = sh[k];
        if (c) atomicAdd(&gh[k], c);
    }

    // ---- last-block-done handshake ----
    __threadfence();
    __syncthreads();
    __shared__ unsigned s_isLast;
    if (threadIdx.x == 0)
        s_isLast = (atomicAdd(&g_done1[m], 1u) == gridDim.x - 1u) ? 1u : 0u;
    __syncthreads();
    if (!s_isLast) return;
    __threadfence();

    // ---- select1: find prefix bin containing rank j ----
    constexpr int PER = H1_BINS / G1T;  // 16
    unsigned bins[PER];
    unsigned local = 0;
    const int base = threadIdx.x * PER;
#pragma unroll
    for (int q = 0; q < PER; q++) {
        bins[q] = gh[base + q];
        local += bins[q];
    }
    __shared__ unsigned s_scan[G1T];
    s_scan[threadIdx.x] = local;
    __syncthreads();
    for (int off = 1; off < G1T; off <<= 1) {
        unsigned t = (threadIdx.x >= off) ? s_scan[threadIdx.x - off] : 0u;
        __syncthreads();
        s_scan[threadIdx.x] += t;
        __syncthreads();
    }
    const unsigned incl = s_scan[threadIdx.x];
    const unsigned excl = incl - local;
    if (j >= excl && j < incl) {
        unsigned acc = excl;
#pragma unroll
        for (int q = 0; q < PER; q++) {
            if (j < acc + bins[q]) {
                g_state[m].prefix = (unsigned)(base + q);
                g_state[m].rem1 = j - acc;
                break;
            }
            acc += bins[q];
        }
    }
    if (threadIdx.x == 0) g_done1[m] = 0;  // reset for next replay
}

// ---------------------------------------------------------------------------
// K2: 18-bit fine + 10-bit coarse histogram within prefix + 2-level select2
// ---------------------------------------------------------------------------
__global__ __launch_bounds__(G2T) void hist2_kernel(
    const float4* __restrict__ A, const float4* __restrict__ B, int n4) {
    const int m = blockIdx.y;
    const float4* src = m ? B : A;
    const unsigned pfx = g_state[m].prefix;
    unsigned* gh = g_hist2[m];
    unsigned* gc = g_hist2c[m];

    const int stride = G2T * gridDim.x;
    for (int i = blockIdx.x * G2T + threadIdx.x; i < n4; i += stride) {
        float4 v = __ldg(src + i);
        unsigned b;
        b = __float_as_uint(v.x) & ABS_MASK;
        if ((b >> H2_BITS) == pfx) {
            unsigned f = b & (H2_BINS - 1);
            atomicAdd(&gh[f], 1u);
            atomicAdd(&gc[f >> 8], 1u);
        }
        b = __float_as_uint(v.y) & ABS_MASK;
        if ((b >> H2_BITS) == pfx) {
            unsigned f = b & (H2_BINS - 1);
            atomicAdd(&gh[f], 1u);
            atomicAdd(&gc[f >> 8], 1u);
        }
        b = __float_as_uint(v.z) & ABS_MASK;
        if ((b >> H2_BITS) == pfx) {
            unsigned f = b & (H2_BINS - 1);
            atomicAdd(&gh[f], 1u);
            atomicAdd(&gc[f >> 8], 1u);
        }
        b = __float_as_uint(v.w) & ABS_MASK;
        if ((b >> H2_BITS) == pfx) {
            unsigned f = b & (H2_BINS - 1);
            atomicAdd(&gh[f], 1u);
            atomicAdd(&gc[f >> 8], 1u);
        }
    }

    // ---- last-block-done handshake ----
    __threadfence();
    __syncthreads();
    __shared__ unsigned s_isLast;
    if (threadIdx.x == 0)
        s_isLast = (atomicAdd(&g_done2[m], 1u) == gridDim.x - 1u) ? 1u : 0u;
    __syncthreads();
    if (!s_isLast) return;
    __threadfence();

    const unsigned rank = g_state[m].rem1;
    const int tid = threadIdx.x;
    __shared__ unsigned s_scan2[G2T];
    __shared__ unsigned s_cb, s_remc;

    // ---- level 1: scan 1024 coarse bins (4 per thread, uint4) ----
    {
        uint4 cv = ((const uint4*)gc)[tid];
        unsigned local = cv.x + cv.y + cv.z + cv.w;
        s_scan2[tid] = local;
        __syncthreads();
        for (int off = 1; off < G2T; off <<= 1) {
            unsigned t = (tid >= off) ? s_scan2[tid - off] : 0u;
            __syncthreads();
            s_scan2[tid] += t;
            __syncthreads();
        }
        const unsigned incl = s_scan2[tid];
        const unsigned excl = incl - local;
        if (rank >= excl && rank < incl) {
            unsigned acc = excl;
            unsigned c0 = cv.x, c1 = cv.y, c2 = cv.z, c3 = cv.w;
            int q = 0;
            if (rank >= acc + c0) { acc += c0; q = 1;
                if (rank >= acc + c1) { acc += c1; q = 2;
                    if (rank >= acc + c2) { acc += c2; q = 3; } } }
            s_cb = (unsigned)(tid * 4 + q);
            s_remc = rank - acc;
        }
        __syncthreads();
    }
    const unsigned cb = s_cb;
    const unsigned remc = s_remc;
    __syncthreads();

    // ---- level 2: scan the 256 fine bins of coarse bucket cb ----
    {
        unsigned local = gh[cb * 256u + (unsigned)tid];
        s_scan2[tid] = local;
        __syncthreads();
        for (int off = 1; off < G2T; off <<= 1) {
            unsigned t = (tid >= off) ? s_scan2[tid - off] : 0u;
            __syncthreads();
            s_scan2[tid] += t;
            __syncthreads();
        }
        const unsigned incl = s_scan2[tid];
        const unsigned excl = incl - local;
        if (remc >= excl && remc < incl) {
            const unsigned fine = cb * 256u + (unsigned)tid;
            g_state[m].T32 = (pfx << H2_BITS) | fine;
            g_state[m].r = remc - excl;
        }
    }
    if (threadIdx.x == 0) g_done2[m] = 0;  // reset for next replay
}

// ---------------------------------------------------------------------------
// K3: mask write (strict >) + tie collection + hist zeroing + fused tie fix
// ---------------------------------------------------------------------------
__global__ __launch_bounds__(GMT) void mask_kernel(
    const float4* __restrict__ A, const float4* __restrict__ B,
    float4* __restrict__ out, int n4) {
    const int m = blockIdx.y;
    const float4* src = m ? B : A;
    float4* dst = out + (size_t)m * (size_t)n4;
    const unsigned T = g_state[m].T32;

    const int stride = GMT * gridDim.x;
    for (int i = blockIdx.x * GMT + threadIdx.x; i < n4; i += stride) {
        float4 v = __ldg(src + i);
        unsigned bx = __float_as_uint(v.x) & ABS_MASK;
        unsigned by = __float_as_uint(v.y) & ABS_MASK;
        unsigned bz = __float_as_uint(v.z) & ABS_MASK;
        unsigned bw = __float_as_uint(v.w) & ABS_MASK;
        float4 o;
        o.x = (bx > T) ? 1.0f : 0.0f;
        o.y = (by > T) ? 1.0f : 0.0f;
        o.z = (bz > T) ? 1.0f : 0.0f;
        o.w = (bw > T) ? 1.0f : 0.0f;
        dst[i] = o;
        // exact-equality ties are extremely sparse (~1-16 per matrix)
        if (bx == T || by == T || bz == T || bw == T) {
            const unsigned idx = 4u * (unsigned)i;
            if (bx == T) {
                unsigned p = atomicAdd(&g_tie_cnt[m], 1u);
                if (p < TIE_CAP) g_tie_idx[m][p] = idx + 0u;
            }
            if (by == T) {
                unsigned p = atomicAdd(&g_tie_cnt[m], 1u);
                if (p < TIE_CAP) g_tie_idx[m][p] = idx + 1u;
            }
            if (bz == T) {
                unsigned p = atomicAdd(&g_tie_cnt[m], 1u);
                if (p < TIE_CAP) g_tie_idx[m][p] = idx + 2u;
            }
            if (bw == T) {
                unsigned p = atomicAdd(&g_tie_cnt[m], 1u);
                if (p < TIE_CAP) g_tie_idx[m][p] = idx + 3u;
            }
        }
    }

    // zero histograms for the next graph replay (not read again this replay)
    {
        const int tid = ((int)blockIdx.y * (int)gridDim.x + (int)blockIdx.x) * GMT
                        + (int)threadIdx.x;
        const int tot = (int)gridDim.x * 2 * GMT;
        unsigned* h2 = &g_hist2[0][0];
        for (int k = tid; k < 2 * H2_BINS; k += tot) h2[k] = 0;
        unsigned* h1 = &g_hist1[0][0];
        for (int k = tid; k < 2 * H1_BINS; k += tot) h1[k] = 0;
        unsigned* hc = &g_hist2c[0][0];
        for (int k = tid; k < 2 * H2C_BINS; k += tot) hc[k] = 0;
    }

    // ---- last-block-done handshake, then in-place tie resolution ----
    __threadfence();
    __syncthreads();
    __shared__ unsigned s_isLast;
    if (threadIdx.x == 0)
        s_isLast = (atomicAdd(&g_done3[m], 1u) == gridDim.x - 1u) ? 1u : 0u;
    __syncthreads();
    if (!s_isLast) return;
    __threadfence();

    unsigned tc = g_tie_cnt[m];
    if (tc > TIE_CAP) tc = TIE_CAP;
    const unsigned r = g_state[m].r;
    float* dstf = (float*)(out) + (size_t)m * (size_t)n4 * 4u;
    for (unsigned e = threadIdx.x; e < tc; e += GMT) {
        const unsigned my = g_tie_idx[m][e];
        unsigned rk = 0;
        for (unsigned k = 0; k < tc; k++)
            rk += (g_tie_idx[m][k] < my) ? 1u : 0u;
        if (rk >= r) dstf[my] = 1.0f;
    }
    __syncthreads();
    if (threadIdx.x == 0) {
        g_tie_cnt[m] = 0;  // reset for next replay
        g_done3[m] = 0;
    }
}

// ---------------------------------------------------------------------------
extern "C" void kernel_launch(void* const* d_in, const int* in_sizes, int n_in,
                              void* d_out, int out_size) {
    const float4* A = (const float4*)d_in[0];
    const float4* B = (const float4*)d_in[1];
    float4* out = (float4*)d_out;

    const unsigned n = (unsigned)in_sizes[0];  // 16,777,216 per matrix
    const int n4 = (int)(n / 4u);
    // Mirror Python int((1.0 - 0.1) * n) exactly (double arithmetic, truncate)
    const unsigned j = (unsigned)((1.0 - 0.1) * (double)n);

    dim3 g1(G1X, 2);
    hist1_kernel<<<g1, G1T>>>(A, B, n4, j);

    dim3 g2(G2X, 2);
    hist2_kernel<<<g2, G2T>>>(A, B, n4);

    dim3 gm(GMX, 2);
    mask_kernel<<<gm, GMT>>>(A, B, out, n4);
}